// round 12
// baseline (speedup 1.0000x reference)
#include <cuda_runtime.h>
#include <cuda_bf16.h>
#include <cstdint>

#define Bb 4
#define Nn 2048
#define Ff 256
#define Tt 8
#define Hh 4
#define Dd 64
#define FT 264
#define BH (Bb*Hh)      // 16
#define BHN (BH*Nn)     // 32768

// ---- scratch (static device globals; no allocation) ----
__device__ float g_v1[Hh*FT];
__device__ float g_v2[Hh*FT];
__device__ float g_u[BHN];
__device__ float g_E1[BHN];
__device__ float g_F1[BHN];
__device__ float g_vv[BHN];
__device__ float g_SE[BHN];
__device__ float g_SF[BHN];
__device__ float4 g_cf[BHN];            // (vv, c1, c2, 0)
__device__ uint32_t g_adjb[Bb*Nn*64];   // 2MB bitmask
__device__ float g_Wh[BH*Nn*Dd];        // 8MB: Wh[bh][n][d], tf32-RN pre-rounded

// mma.sync tf32 m16n8k8 (sm_80+, plain sm_103 target OK)
#define MMA_TF32(d, a0,a1,a2,a3, b0,b1) \
  asm volatile("mma.sync.aligned.m16n8k8.row.col.f32.tf32.tf32.f32 " \
    "{%0,%1,%2,%3}, {%4,%5,%6,%7}, {%8,%9}, {%0,%1,%2,%3};" \
    : "+f"((d)[0]),"+f"((d)[1]),"+f"((d)[2]),"+f"((d)[3]) \
    : "r"(a0),"r"(a1),"r"(a2),"r"(a3),"r"(b0),"r"(b1))

__device__ __forceinline__ uint32_t tf32_rn_bits(float f){
  uint32_t u; asm("cvt.rna.tf32.f32 %0, %1;" : "=r"(u) : "f"(f)); return u;
}
__device__ __forceinline__ float tf32_rn(float f){
  return __uint_as_float(tf32_rn_bits(f));
}
__device__ __forceinline__ void tf32_split(float f, uint32_t& hi, uint32_t& lo){
  hi = tf32_rn_bits(f);
  float r = f - __uint_as_float(hi);
  lo = tf32_rn_bits(r);
}

// ---- K0: v1/v2 GEMVs + zero SE/SF (graph-replay safe) ----
__global__ void k0_init(const float* __restrict__ Wq, const float* __restrict__ Wk,
                        const float* __restrict__ a){
  int idx = blockIdx.x*blockDim.x + threadIdx.x;
  if (idx < BHN){ g_SE[idx] = 0.f; g_SF[idx] = 0.f; }
  if (idx >= Hh*FT) return;
  int h = idx / FT, f = idx - h*FT;
  const float* wq = Wq + (h*FT + f)*Dd;
  const float* wk = Wk + (h*FT + f)*Dd;
  const float* a1 = a + h*2*Dd;
  const float* a2 = a1 + Dd;
  float s1 = 0.f, s2 = 0.f;
  #pragma unroll
  for (int d = 0; d < Dd; d++){ s1 += wq[d]*a1[d]; s2 += wk[d]*a2[d]; }
  g_v1[idx] = s1; g_v2[idx] = s2;
}

// ---- K1P: fused [adj->bitmask pack] + [Wh tf32x3 GEMM + e1/e2 GEMVs] ----
// blocks 0..255: pack (32 rows each). blocks 256..511: GEMM tiles.
__global__ void __launch_bounds__(256) k1p(const float* __restrict__ x,
                                           const float* __restrict__ W,
                                           const float* __restrict__ toh,
                                           const int* __restrict__ adj){
  __shared__ float As[128*36];            // [m][k] pad 36
  __shared__ float Bs[32*72];             // [k][d] pad 72
  __shared__ float sv1[FT], sv2[FT];
  __shared__ float sdq[256], sdk[256];

  int tid = threadIdx.x, wid = tid>>5, lane = tid&31;

  if (blockIdx.x < 256){
    // ---------- pack: 32 rows per block, 4 rows per warp ----------
    int base_row = blockIdx.x*32 + wid*4;
    #pragma unroll
    for (int r = 0; r < 4; ++r){
      int row = base_row + r;
      const int* rp = adj + (size_t)row*Nn;
      uint32_t* op = g_adjb + (size_t)row*64;
      #pragma unroll 4
      for (int w = 0; w < 64; ++w){
        int v = rp[w*32 + lane];
        uint32_t m = __ballot_sync(0xffffffffu, v != 0);
        if (lane == 0) op[w] = m;
      }
    }
    return;
  }

  // ---------- GEMM tile ----------
  int idx5 = blockIdx.x - 256;            // 0..255
  int bx = idx5 & 15, h = (idx5 >> 4) & 3, b = idx5 >> 6;
  int m0 = bx*128;
  int bh = b*Hh + h;
  int wm = wid>>1, wn = wid&1, gid = lane>>2, tig = lane&3;
  for (int i = tid; i < FT; i += 256){ sv1[i]=g_v1[h*FT+i]; sv2[i]=g_v2[h*FT+i]; }

  int am = tid>>1, akh = (tid&1)*16;      // A staging: row, k-half
  int bk = tid>>3, bd0 = (tid&7)*8;       // B staging: k row, d group
  const float* xrow = &x[((size_t)(b*Nn)+m0+am)*Ff];

  float acc[2][4][4];
  #pragma unroll
  for (int mt=0;mt<2;mt++)
    #pragma unroll
    for (int nt=0;nt<4;nt++)
      #pragma unroll
      for (int e=0;e<4;e++) acc[mt][nt][e]=0.f;
  float dq = 0.f, dk = 0.f;

  float4 ra[4]; float4 rb0, rb1;
  #pragma unroll
  for (int q=0;q<4;q++) ra[q] = *(const float4*)&xrow[akh + q*4];
  {
    const float* wp = &W[((size_t)h*Ff + bk)*Dd + bd0];
    rb0 = *(const float4*)wp; rb1 = *(const float4*)(wp+4);
  }

  for (int c = 0; c < 8; ++c){
    __syncthreads();
    #pragma unroll
    for (int q=0;q<4;q++){
      *(float4*)&As[am*36 + akh + q*4] = ra[q];
      int k = c*32 + akh + q*4;
      dq += ra[q].x*sv1[k+0] + ra[q].y*sv1[k+1] + ra[q].z*sv1[k+2] + ra[q].w*sv1[k+3];
      dk += ra[q].x*sv2[k+0] + ra[q].y*sv2[k+1] + ra[q].z*sv2[k+2] + ra[q].w*sv2[k+3];
    }
    *(float4*)&Bs[bk*72 + bd0]     = rb0;
    *(float4*)&Bs[bk*72 + bd0 + 4] = rb1;
    if (c < 7){
      #pragma unroll
      for (int q=0;q<4;q++) ra[q] = *(const float4*)&xrow[(c+1)*32 + akh + q*4];
      const float* wp = &W[((size_t)h*Ff + (c+1)*32 + bk)*Dd + bd0];
      rb0 = *(const float4*)wp; rb1 = *(const float4*)(wp+4);
    }
    __syncthreads();
    #pragma unroll
    for (int ks = 0; ks < 4; ++ks){
      uint32_t ah[2][4], al[2][4];
      #pragma unroll
      for (int mt=0;mt<2;mt++){
        int r = wm*32 + 16*mt + gid;
        float f0 = As[r*36     + ks*8 + tig];
        float f1 = As[(r+8)*36 + ks*8 + tig];
        float f2 = As[r*36     + ks*8 + tig + 4];
        float f3 = As[(r+8)*36 + ks*8 + tig + 4];
        tf32_split(f0, ah[mt][0], al[mt][0]);
        tf32_split(f1, ah[mt][1], al[mt][1]);
        tf32_split(f2, ah[mt][2], al[mt][2]);
        tf32_split(f3, ah[mt][3], al[mt][3]);
      }
      uint32_t bhh[4][2], bll[4][2];
      #pragma unroll
      for (int nt=0;nt<4;nt++){
        int n = wn*32 + nt*8 + gid;
        float f0 = Bs[(ks*8+tig)*72 + n];
        float f1 = Bs[(ks*8+tig+4)*72 + n];
        tf32_split(f0, bhh[nt][0], bll[nt][0]);
        tf32_split(f1, bhh[nt][1], bll[nt][1]);
      }
      #pragma unroll
      for (int mt=0;mt<2;mt++)
        #pragma unroll
        for (int nt=0;nt<4;nt++){
          MMA_TF32(acc[mt][nt], ah[mt][0],ah[mt][1],ah[mt][2],ah[mt][3], bhh[nt][0],bhh[nt][1]);
          MMA_TF32(acc[mt][nt], ah[mt][0],ah[mt][1],ah[mt][2],ah[mt][3], bll[nt][0],bll[nt][1]);
          MMA_TF32(acc[mt][nt], al[mt][0],al[mt][1],al[mt][2],al[mt][3], bhh[nt][0],bhh[nt][1]);
        }
    }
  }
  if (akh == 16){
    const float* tp = &toh[((size_t)(b*Nn)+m0+am)*Tt];
    #pragma unroll
    for (int t=0;t<8;t++){ float tv = tp[t]; dq += tv*sv1[Ff+t]; dk += tv*sv2[Ff+t]; }
  }
  sdq[tid] = dq; sdk[tid] = dk;
  __syncthreads();
  if (tid < 128){
    float q  = sdq[tid*2] + sdq[tid*2+1];
    float kk = sdk[tid*2] + sdk[tid*2+1];
    int idx = bh*Nn + m0 + tid;
    g_u[idx]  = q;
    g_E1[idx] = __expf(q);
    g_F1[idx] = __expf(0.2f*q);
    g_vv[idx] = kk;
  }
  #pragma unroll
  for (int mt=0;mt<2;mt++){
    int r = m0 + wm*32 + 16*mt + gid;
    #pragma unroll
    for (int nt=0;nt<4;nt++){
      int col = wn*32 + nt*8 + tig*2;
      float2 v0, v1;
      v0.x = tf32_rn(acc[mt][nt][0]); v0.y = tf32_rn(acc[mt][nt][1]);
      v1.x = tf32_rn(acc[mt][nt][2]); v1.y = tf32_rn(acc[mt][nt][3]);
      *(float2*)&g_Wh[((size_t)bh*Nn + r)*Dd + col]     = v0;
      *(float2*)&g_Wh[((size_t)bh*Nn + r + 8)*Dd + col] = v1;
    }
  }
}

// ---- K2: column stats (i-chunk 128 -> 512 CTAs for occupancy) ----
__global__ void __launch_bounds__(256) k2_stats(){
  __shared__ float4 sPack[512];           // [h][ii] = (u, E, F, 0), ii<128
  __shared__ uint32_t sB[1024];           // [ii][w], ii<128
  int tid = threadIdx.x;
  int jt = blockIdx.x, ic = blockIdx.y, b = blockIdx.z;
  int i0 = ic*128;
  for (int i = tid; i < 512; i += 256){
    int h = i >> 7, ii = i & 127;
    int idx = (b*Hh + h)*Nn + i0 + ii;
    sPack[i] = make_float4(g_u[idx], g_E1[idx], g_F1[idx], 0.f);
  }
  for (int idx = tid; idx < 1024; idx += 256){
    int ii = idx >> 3, w = idx & 7;
    sB[idx] = g_adjb[(size_t)(b*Nn + i0 + ii)*64 + jt*8 + w];
  }
  __syncthreads();
  int j = jt*256 + tid;
  int jw = tid >> 5, jb = tid & 31;
  float nv[4], SEr[4]={0,0,0,0}, SFr[4]={0,0,0,0};
  #pragma unroll
  for (int h=0;h<4;h++) nv[h] = -g_vv[(b*Hh+h)*Nn + j];
  #pragma unroll 4
  for (int ii = 0; ii < 128; ii++){
    uint32_t word = sB[ii*8 + jw];
    float bf = (float)((word >> jb) & 1u);
    #pragma unroll
    for (int h=0;h<4;h++){
      float4 pk = sPack[h*128 + ii];
      bool pos = pk.x > nv[h];
      SEr[h] += bf * (pos ? pk.y : 0.f);
      SFr[h] += bf * (pos ? 0.f : pk.z);
    }
  }
  #pragma unroll
  for (int h=0;h<4;h++){
    atomicAdd(&g_SE[(b*Hh+h)*Nn + j], SEr[h]);
    atomicAdd(&g_SF[(b*Hh+h)*Nn + j], SFr[h]);
  }
}

// ---- K2b: packed coefficients ----
__global__ void k2b_c(){
  int idx = blockIdx.x*blockDim.x + threadIdx.x;
  if (idx >= BHN) return;
  float v  = g_vv[idx];
  float ev = __expf(v), ef = __expf(0.2f*v);
  float den = ev*g_SE[idx] + ef*g_SF[idx];
  float inv = (den > 0.f) ? (1.f/den) : 0.f;
  g_cf[idx] = make_float4(v, ev*inv, ef*inv, 0.f);
}

// ---- K3: out = elu(P @ Wh); 8 warps each own 16 M-rows x full N=64 ----
// (removes the duplicated A-fragment generation of the 4x2 layout)
__global__ void __launch_bounds__(256) k3_mma(float* __restrict__ out){
  __shared__ float Bs[2][32*72];          // [k(j)][d] pad 72, conflict-free
  __shared__ float4 scf[2][32];
  __shared__ uint32_t sAdj[2][128];
  int b = blockIdx.z, h = blockIdx.y, i0 = blockIdx.x*128;
  int bh = b*Hh + h;
  int tid = threadIdx.x, wid = tid>>5, lane = tid&31;
  int gid = lane >> 2, tig = lane & 3;

  float ui[2], Ei[2], Fi[2];
  #pragma unroll
  for (int q=0;q<2;q++){
    int idx = bh*Nn + i0 + wid*16 + gid + 8*q;
    ui[q] = g_u[idx]; Ei[q] = g_E1[idx]; Fi[q] = g_F1[idx];
  }
  int sj = tid >> 3, sd0 = (tid & 7) * 8;

  {
    const float* wp = &g_Wh[((size_t)bh*Nn + sj)*Dd + sd0];
    float4 x0 = *(const float4*)wp, x1 = *(const float4*)(wp+4);
    *(float4*)&Bs[0][sj*72 + sd0]     = x0;
    *(float4*)&Bs[0][sj*72 + sd0 + 4] = x1;
    if (tid < 32) scf[0][tid] = g_cf[bh*Nn + tid];
    if (tid >= 64 && tid < 192) sAdj[0][tid-64] = g_adjb[(size_t)(b*Nn + i0 + tid-64)*64];
  }
  __syncthreads();

  float acc[8][4];
  #pragma unroll
  for (int nt=0;nt<8;nt++)
    #pragma unroll
    for (int e=0;e<4;e++) acc[nt][e]=0.f;

  for (int c = 0; c < 64; ++c){
    int p = c & 1;
    if (c < 63){
      int s = p ^ 1, cn = c + 1;
      const float* wp = &g_Wh[((size_t)bh*Nn + cn*32 + sj)*Dd + sd0];
      float4 x0 = *(const float4*)wp, x1 = *(const float4*)(wp+4);
      *(float4*)&Bs[s][sj*72 + sd0]     = x0;
      *(float4*)&Bs[s][sj*72 + sd0 + 4] = x1;
      if (tid < 32) scf[s][tid] = g_cf[bh*Nn + cn*32 + tid];
      if (tid >= 64 && tid < 192) sAdj[s][tid-64] = g_adjb[(size_t)(b*Nn + i0 + tid-64)*64 + cn];
    }
    uint32_t w0 = sAdj[p][wid*16 + gid];
    uint32_t w1 = sAdj[p][wid*16 + gid + 8];

    #pragma unroll
    for (int ks = 0; ks < 4; ++ks){
      float4 coA = scf[p][ks*8 + tig];
      float4 coB = scf[p][ks*8 + tig + 4];
      int jlA = ks*8 + tig, jlB = jlA + 4;
      uint32_t a0,a1,a2,a3;
      {
        float s0 = ui[0] + coA.x;
        float t0 = (s0 > 0.f) ? Ei[0]*coA.y : Fi[0]*coA.z;
        a0 = ((w0>>jlA)&1u) ? tf32_rn_bits(t0) : 0u;
        float s1 = ui[1] + coA.x;
        float t1 = (s1 > 0.f) ? Ei[1]*coA.y : Fi[1]*coA.z;
        a1 = ((w1>>jlA)&1u) ? tf32_rn_bits(t1) : 0u;
        float s2 = ui[0] + coB.x;
        float t2 = (s2 > 0.f) ? Ei[0]*coB.y : Fi[0]*coB.z;
        a2 = ((w0>>jlB)&1u) ? tf32_rn_bits(t2) : 0u;
        float s3 = ui[1] + coB.x;
        float t3 = (s3 > 0.f) ? Ei[1]*coB.y : Fi[1]*coB.z;
        a3 = ((w1>>jlB)&1u) ? tf32_rn_bits(t3) : 0u;
      }
      #pragma unroll
      for (int nt=0;nt<8;nt++){
        int n = nt*8 + gid;
        uint32_t b0 = __float_as_uint(Bs[p][(ks*8+tig)*72 + n]);
        uint32_t b1 = __float_as_uint(Bs[p][(ks*8+tig+4)*72 + n]);
        MMA_TF32(acc[nt], a0,a1,a2,a3, b0,b1);
      }
    }
    __syncthreads();
  }

  // epilogue: ELU + store (rows wid*16+gid, +8)
  int r0 = i0 + wid*16 + gid;
  #pragma unroll
  for (int nt=0;nt<8;nt++){
    int d0 = h*Dd + nt*8 + tig*2;
    float t;
    float2 o01, o23;
    t = acc[nt][0]; o01.x = (t > 0.f) ? t : (__expf(t)-1.f);
    t = acc[nt][1]; o01.y = (t > 0.f) ? t : (__expf(t)-1.f);
    t = acc[nt][2]; o23.x = (t > 0.f) ? t : (__expf(t)-1.f);
    t = acc[nt][3]; o23.y = (t > 0.f) ? t : (__expf(t)-1.f);
    *(float2*)&out[(size_t)(b*Nn + r0    )*(Hh*Dd) + d0] = o01;
    *(float2*)&out[(size_t)(b*Nn + r0 + 8)*(Hh*Dd) + d0] = o23;
  }
}

extern "C" void kernel_launch(void* const* d_in, const int* in_sizes, int n_in,
                              void* d_out, int out_size) {
  const float* x   = (const float*)d_in[0];  // (4,2048,256)
  const int*   adj = (const int*)  d_in[1];  // (4,2048,2048)
  const float* toh = (const float*)d_in[2];  // (4,2048,8)
  const float* Wq  = (const float*)d_in[3];  // (4,264,64)
  const float* Wk  = (const float*)d_in[4];  // (4,264,64)
  const float* W   = (const float*)d_in[5];  // (4,256,64)
  const float* a   = (const float*)d_in[6];  // (4,128,1)
  float* out = (float*)d_out;                // (4,2048,1024) fp32

  k0_init<<<128, 256>>>(Wq, Wk, a);
  k1p<<<512, 256>>>(x, W, toh, adj);
  k2_stats<<<dim3(8, 16, 4), 256>>>();
  k2b_c<<<128, 256>>>();
  k3_mma<<<dim3(16, Hh, Bb), 256>>>(out);
}

// round 16
// speedup vs baseline: 1.0413x; 1.0413x over previous
#include <cuda_runtime.h>
#include <cuda_bf16.h>
#include <cstdint>

#define Bb 4
#define Nn 2048
#define Ff 256
#define Tt 8
#define Hh 4
#define Dd 64
#define FT 264
#define BH (Bb*Hh)      // 16
#define BHN (BH*Nn)     // 32768

// ---- scratch (static device globals; no allocation) ----
__device__ float g_v1[Hh*FT];
__device__ float g_v2[Hh*FT];
__device__ float g_u[BHN];
__device__ float g_E1[BHN];
__device__ float g_F1[BHN];
__device__ float g_vv[BHN];
__device__ float g_SE[BHN];
__device__ float g_SF[BHN];
__device__ uint32_t g_adjb[Bb*Nn*64];   // 2MB bitmask
__device__ float g_Wh[BH*Nn*Dd];        // 8MB: Wh[bh][n][d], tf32-RN pre-rounded

// mma.sync tf32 m16n8k8 (sm_80+, plain sm_103 target OK)
#define MMA_TF32(d, a0,a1,a2,a3, b0,b1) \
  asm volatile("mma.sync.aligned.m16n8k8.row.col.f32.tf32.tf32.f32 " \
    "{%0,%1,%2,%3}, {%4,%5,%6,%7}, {%8,%9}, {%0,%1,%2,%3};" \
    : "+f"((d)[0]),"+f"((d)[1]),"+f"((d)[2]),"+f"((d)[3]) \
    : "r"(a0),"r"(a1),"r"(a2),"r"(a3),"r"(b0),"r"(b1))

__device__ __forceinline__ uint32_t tf32_rn_bits(float f){
  uint32_t u; asm("cvt.rna.tf32.f32 %0, %1;" : "=r"(u) : "f"(f)); return u;
}
__device__ __forceinline__ float tf32_rn(float f){
  return __uint_as_float(tf32_rn_bits(f));
}
__device__ __forceinline__ void tf32_split(float f, uint32_t& hi, uint32_t& lo){
  hi = tf32_rn_bits(f);
  float r = f - __uint_as_float(hi);
  lo = tf32_rn_bits(r);
}

// ---- K0: v1/v2 GEMVs + zero SE/SF (graph-replay safe) ----
__global__ void k0_init(const float* __restrict__ Wq, const float* __restrict__ Wk,
                        const float* __restrict__ a){
  int idx = blockIdx.x*blockDim.x + threadIdx.x;
  if (idx < BHN){ g_SE[idx] = 0.f; g_SF[idx] = 0.f; }
  if (idx >= Hh*FT) return;
  int h = idx / FT, f = idx - h*FT;
  const float* wq = Wq + (h*FT + f)*Dd;
  const float* wk = Wk + (h*FT + f)*Dd;
  const float* a1 = a + h*2*Dd;
  const float* a2 = a1 + Dd;
  float s1 = 0.f, s2 = 0.f;
  #pragma unroll
  for (int d = 0; d < Dd; d++){ s1 += wq[d]*a1[d]; s2 += wk[d]*a2[d]; }
  g_v1[idx] = s1; g_v2[idx] = s2;
}

// ---- K_pack: adj -> bitmask ----
__global__ void __launch_bounds__(256) k_pack(const int* __restrict__ adj){
  int grow = (blockIdx.x*256 + threadIdx.x) >> 5;
  int lane = threadIdx.x & 31;
  const int* rp = adj + (size_t)grow*Nn;
  uint32_t* op = g_adjb + grow*64;
  #pragma unroll 4
  for (int w = 0; w < 64; w++){
    int v = rp[w*32 + lane];
    uint32_t m = __ballot_sync(0xffffffffu, v != 0);
    if (lane == 0) op[w] = m;
  }
}

// ---- K1: Wh[bh][n][d] via tf32x3 mma.sync; fused e1/e2 GEMVs ----
__global__ void __launch_bounds__(256) k1_wh(const float* __restrict__ x,
                                             const float* __restrict__ W,
                                             const float* __restrict__ toh){
  __shared__ float As[128*36];            // [m][k] pad 36
  __shared__ float Bs[32*72];             // [k][d] pad 72
  __shared__ float sv1[FT], sv2[FT];
  __shared__ float sdq[256], sdk[256];
  int bx = blockIdx.x, h = blockIdx.y, b = blockIdx.z;
  int m0 = bx*128;
  int bh = b*Hh + h;
  int tid = threadIdx.x, wid = tid>>5, lane = tid&31;
  int wm = wid>>1, wn = wid&1, gid = lane>>2, tig = lane&3;
  for (int i = tid; i < FT; i += 256){ sv1[i]=g_v1[h*FT+i]; sv2[i]=g_v2[h*FT+i]; }

  int am = tid>>1, akh = (tid&1)*16;      // A staging: row, k-half
  int bk = tid>>3, bd0 = (tid&7)*8;       // B staging: k row, d group
  const float* xrow = &x[((size_t)(b*Nn)+m0+am)*Ff];

  float acc[2][4][4];
  #pragma unroll
  for (int mt=0;mt<2;mt++)
    #pragma unroll
    for (int nt=0;nt<4;nt++)
      #pragma unroll
      for (int e=0;e<4;e++) acc[mt][nt][e]=0.f;
  float dq = 0.f, dk = 0.f;

  float4 ra[4]; float4 rb0, rb1;
  #pragma unroll
  for (int q=0;q<4;q++) ra[q] = *(const float4*)&xrow[akh + q*4];
  {
    const float* wp = &W[((size_t)h*Ff + bk)*Dd + bd0];
    rb0 = *(const float4*)wp; rb1 = *(const float4*)(wp+4);
  }

  for (int c = 0; c < 8; ++c){
    __syncthreads();
    #pragma unroll
    for (int q=0;q<4;q++){
      *(float4*)&As[am*36 + akh + q*4] = ra[q];
      int k = c*32 + akh + q*4;
      dq += ra[q].x*sv1[k+0] + ra[q].y*sv1[k+1] + ra[q].z*sv1[k+2] + ra[q].w*sv1[k+3];
      dk += ra[q].x*sv2[k+0] + ra[q].y*sv2[k+1] + ra[q].z*sv2[k+2] + ra[q].w*sv2[k+3];
    }
    *(float4*)&Bs[bk*72 + bd0]     = rb0;
    *(float4*)&Bs[bk*72 + bd0 + 4] = rb1;
    if (c < 7){
      #pragma unroll
      for (int q=0;q<4;q++) ra[q] = *(const float4*)&xrow[(c+1)*32 + akh + q*4];
      const float* wp = &W[((size_t)h*Ff + (c+1)*32 + bk)*Dd + bd0];
      rb0 = *(const float4*)wp; rb1 = *(const float4*)(wp+4);
    }
    __syncthreads();
    #pragma unroll
    for (int ks = 0; ks < 4; ++ks){
      uint32_t ah[2][4], al[2][4];
      #pragma unroll
      for (int mt=0;mt<2;mt++){
        int r = wm*32 + 16*mt + gid;
        float f0 = As[r*36     + ks*8 + tig];
        float f1 = As[(r+8)*36 + ks*8 + tig];
        float f2 = As[r*36     + ks*8 + tig + 4];
        float f3 = As[(r+8)*36 + ks*8 + tig + 4];
        tf32_split(f0, ah[mt][0], al[mt][0]);
        tf32_split(f1, ah[mt][1], al[mt][1]);
        tf32_split(f2, ah[mt][2], al[mt][2]);
        tf32_split(f3, ah[mt][3], al[mt][3]);
      }
      uint32_t bhh[4][2], bll[4][2];
      #pragma unroll
      for (int nt=0;nt<4;nt++){
        int n = wn*32 + nt*8 + gid;
        float f0 = Bs[(ks*8+tig)*72 + n];
        float f1 = Bs[(ks*8+tig+4)*72 + n];
        tf32_split(f0, bhh[nt][0], bll[nt][0]);
        tf32_split(f1, bhh[nt][1], bll[nt][1]);
      }
      #pragma unroll
      for (int mt=0;mt<2;mt++)
        #pragma unroll
        for (int nt=0;nt<4;nt++){
          MMA_TF32(acc[mt][nt], ah[mt][0],ah[mt][1],ah[mt][2],ah[mt][3], bhh[nt][0],bhh[nt][1]);
          MMA_TF32(acc[mt][nt], ah[mt][0],ah[mt][1],ah[mt][2],ah[mt][3], bll[nt][0],bll[nt][1]);
          MMA_TF32(acc[mt][nt], al[mt][0],al[mt][1],al[mt][2],al[mt][3], bhh[nt][0],bhh[nt][1]);
        }
    }
  }
  if (akh == 16){
    const float* tp = &toh[((size_t)(b*Nn)+m0+am)*Tt];
    #pragma unroll
    for (int t=0;t<8;t++){ float tv = tp[t]; dq += tv*sv1[Ff+t]; dk += tv*sv2[Ff+t]; }
  }
  sdq[tid] = dq; sdk[tid] = dk;
  __syncthreads();
  if (tid < 128){
    float q  = sdq[tid*2] + sdq[tid*2+1];
    float kk = sdk[tid*2] + sdk[tid*2+1];
    int idx = bh*Nn + m0 + tid;
    g_u[idx]  = q;
    g_E1[idx] = __expf(q);
    g_F1[idx] = __expf(0.2f*q);
    g_vv[idx] = kk;
  }
  #pragma unroll
  for (int mt=0;mt<2;mt++){
    int r = m0 + wm*32 + 16*mt + gid;
    #pragma unroll
    for (int nt=0;nt<4;nt++){
      int col = wn*32 + nt*8 + tig*2;
      float2 v0, v1;
      v0.x = tf32_rn(acc[mt][nt][0]); v0.y = tf32_rn(acc[mt][nt][1]);
      v1.x = tf32_rn(acc[mt][nt][2]); v1.y = tf32_rn(acc[mt][nt][3]);
      *(float2*)&g_Wh[((size_t)bh*Nn + r)*Dd + col]     = v0;
      *(float2*)&g_Wh[((size_t)bh*Nn + r + 8)*Dd + col] = v1;
    }
  }
}

// ---- K2: column stats (i-chunk 128 -> 512 CTAs for occupancy) ----
__global__ void __launch_bounds__(256) k2_stats(){
  __shared__ float4 sPack[512];           // [h][ii] = (u, E, F, 0), ii<128
  __shared__ uint32_t sB[1024];           // [ii][w], ii<128
  int tid = threadIdx.x;
  int jt = blockIdx.x, ic = blockIdx.y, b = blockIdx.z;
  int i0 = ic*128;
  for (int i = tid; i < 512; i += 256){
    int h = i >> 7, ii = i & 127;
    int idx = (b*Hh + h)*Nn + i0 + ii;
    sPack[i] = make_float4(g_u[idx], g_E1[idx], g_F1[idx], 0.f);
  }
  for (int idx = tid; idx < 1024; idx += 256){
    int ii = idx >> 3, w = idx & 7;
    sB[idx] = g_adjb[(size_t)(b*Nn + i0 + ii)*64 + jt*8 + w];
  }
  __syncthreads();
  int j = jt*256 + tid;
  int jw = tid >> 5, jb = tid & 31;
  float nv[4], SEr[4]={0,0,0,0}, SFr[4]={0,0,0,0};
  #pragma unroll
  for (int h=0;h<4;h++) nv[h] = -g_vv[(b*Hh+h)*Nn + j];
  #pragma unroll 4
  for (int ii = 0; ii < 128; ii++){
    uint32_t word = sB[ii*8 + jw];
    float bf = (float)((word >> jb) & 1u);
    #pragma unroll
    for (int h=0;h<4;h++){
      float4 pk = sPack[h*128 + ii];
      bool pos = pk.x > nv[h];
      SEr[h] += bf * (pos ? pk.y : 0.f);
      SFr[h] += bf * (pos ? 0.f : pk.z);
    }
  }
  #pragma unroll
  for (int h=0;h<4;h++){
    atomicAdd(&g_SE[(b*Hh+h)*Nn + j], SEr[h]);
    atomicAdd(&g_SF[(b*Hh+h)*Nn + j], SFr[h]);
  }
}

// ---- K3: out = elu(P @ Wh); 4x2 warp layout; coefficients computed in staging ----
__global__ void __launch_bounds__(256) k3_mma(float* __restrict__ out){
  __shared__ float Bs[2][32*72];          // [k(j)][d] pad 72, conflict-free
  __shared__ float4 scf[2][32];
  __shared__ uint32_t sAdj[2][128];
  int b = blockIdx.z, h = blockIdx.y, i0 = blockIdx.x*128;
  int bh = b*Hh + h;
  int tid = threadIdx.x, wid = tid>>5, lane = tid&31;
  int wm = wid >> 1, wn = wid & 1;
  int gid = lane >> 2, tig = lane & 3;

  float ui[4], Ei[4], Fi[4];
  #pragma unroll
  for (int q=0;q<4;q++){
    int idx = bh*Nn + i0 + wm*32 + gid + 8*q;
    ui[q] = g_u[idx]; Ei[q] = g_E1[idx]; Fi[q] = g_F1[idx];
  }
  int sj = tid >> 3, sd0 = (tid & 7) * 8;  // B staging role

  // prologue: stage chunk 0 into slot 0
  {
    const float* wp = &g_Wh[((size_t)bh*Nn + sj)*Dd + sd0];
    float4 x0 = *(const float4*)wp, x1 = *(const float4*)(wp+4);
    *(float4*)&Bs[0][sj*72 + sd0]     = x0;
    *(float4*)&Bs[0][sj*72 + sd0 + 4] = x1;
    if (tid < 32){
      int idx = bh*Nn + tid;
      float v = g_vv[idx];
      float ev = __expf(v), ef = __expf(0.2f*v);
      float den = ev*g_SE[idx] + ef*g_SF[idx];
      float inv = (den > 0.f) ? __fdividef(1.f, den) : 0.f;
      scf[0][tid] = make_float4(v, ev*inv, ef*inv, 0.f);
    }
    if (tid >= 64 && tid < 192) sAdj[0][tid-64] = g_adjb[(size_t)(b*Nn + i0 + tid-64)*64];
  }
  __syncthreads();

  float acc[2][4][4];
  #pragma unroll
  for (int mt=0;mt<2;mt++)
    #pragma unroll
    for (int nt=0;nt<4;nt++)
      #pragma unroll
      for (int e=0;e<4;e++) acc[mt][nt][e]=0.f;

  for (int c = 0; c < 64; ++c){
    int p = c & 1;
    if (c < 63){
      int s = p ^ 1, cn = c + 1;
      const float* wp = &g_Wh[((size_t)bh*Nn + cn*32 + sj)*Dd + sd0];
      float4 x0 = *(const float4*)wp, x1 = *(const float4*)(wp+4);
      *(float4*)&Bs[s][sj*72 + sd0]     = x0;
      *(float4*)&Bs[s][sj*72 + sd0 + 4] = x1;
      if (tid < 32){
        int idx = bh*Nn + cn*32 + tid;
        float v = g_vv[idx];
        float ev = __expf(v), ef = __expf(0.2f*v);
        float den = ev*g_SE[idx] + ef*g_SF[idx];
        float inv = (den > 0.f) ? __fdividef(1.f, den) : 0.f;
        scf[s][tid] = make_float4(v, ev*inv, ef*inv, 0.f);
      }
      if (tid >= 64 && tid < 192) sAdj[s][tid-64] = g_adjb[(size_t)(b*Nn + i0 + tid-64)*64 + cn];
    }
    uint32_t w4[4];
    #pragma unroll
    for (int q=0;q<4;q++) w4[q] = sAdj[p][wm*32 + gid + 8*q];

    #pragma unroll
    for (int ks = 0; ks < 4; ++ks){
      float4 coA = scf[p][ks*8 + tig];
      float4 coB = scf[p][ks*8 + tig + 4];
      int jlA = ks*8 + tig, jlB = jlA + 4;
      uint32_t bb[4][2];
      #pragma unroll
      for (int nt=0;nt<4;nt++){
        int n = wn*32 + nt*8 + gid;
        bb[nt][0] = __float_as_uint(Bs[p][(ks*8+tig)*72 + n]);
        bb[nt][1] = __float_as_uint(Bs[p][(ks*8+tig+4)*72 + n]);
      }
      #pragma unroll
      for (int mt=0;mt<2;mt++){
        uint32_t a0,a1,a2,a3;
        {
          int q = 2*mt;
          float s0 = ui[q] + coA.x;
          float t0 = (s0 > 0.f) ? Ei[q]*coA.y : Fi[q]*coA.z;
          a0 = ((w4[q]>>jlA)&1u) ? tf32_rn_bits(t0) : 0u;
          float s2 = ui[q] + coB.x;
          float t2 = (s2 > 0.f) ? Ei[q]*coB.y : Fi[q]*coB.z;
          a2 = ((w4[q]>>jlB)&1u) ? tf32_rn_bits(t2) : 0u;
        }
        {
          int q = 2*mt+1;
          float s1 = ui[q] + coA.x;
          float t1 = (s1 > 0.f) ? Ei[q]*coA.y : Fi[q]*coA.z;
          a1 = ((w4[q]>>jlA)&1u) ? tf32_rn_bits(t1) : 0u;
          float s3 = ui[q] + coB.x;
          float t3 = (s3 > 0.f) ? Ei[q]*coB.y : Fi[q]*coB.z;
          a3 = ((w4[q]>>jlB)&1u) ? tf32_rn_bits(t3) : 0u;
        }
        MMA_TF32(acc[mt][0], a0,a1,a2,a3, bb[0][0], bb[0][1]);
        MMA_TF32(acc[mt][1], a0,a1,a2,a3, bb[1][0], bb[1][1]);
        MMA_TF32(acc[mt][2], a0,a1,a2,a3, bb[2][0], bb[2][1]);
        MMA_TF32(acc[mt][3], a0,a1,a2,a3, bb[3][0], bb[3][1]);
      }
    }
    __syncthreads();
  }

  // epilogue: ELU + store
  #pragma unroll
  for (int mt=0;mt<2;mt++){
    int r0 = i0 + wm*32 + 16*mt + gid;
    #pragma unroll
    for (int nt=0;nt<4;nt++){
      int d0 = h*Dd + wn*32 + nt*8 + tig*2;
      float t;
      float2 o01, o23;
      t = acc[mt][nt][0]; o01.x = (t > 0.f) ? t : (__expf(t)-1.f);
      t = acc[mt][nt][1]; o01.y = (t > 0.f) ? t : (__expf(t)-1.f);
      t = acc[mt][nt][2]; o23.x = (t > 0.f) ? t : (__expf(t)-1.f);
      t = acc[mt][nt][3]; o23.y = (t > 0.f) ? t : (__expf(t)-1.f);
      *(float2*)&out[(size_t)(b*Nn + r0    )*(Hh*Dd) + d0] = o01;
      *(float2*)&out[(size_t)(b*Nn + r0 + 8)*(Hh*Dd) + d0] = o23;
    }
  }
}

extern "C" void kernel_launch(void* const* d_in, const int* in_sizes, int n_in,
                              void* d_out, int out_size) {
  const float* x   = (const float*)d_in[0];  // (4,2048,256)
  const int*   adj = (const int*)  d_in[1];  // (4,2048,2048)
  const float* toh = (const float*)d_in[2];  // (4,2048,8)
  const float* Wq  = (const float*)d_in[3];  // (4,264,64)
  const float* Wk  = (const float*)d_in[4];  // (4,264,64)
  const float* W   = (const float*)d_in[5];  // (4,256,64)
  const float* a   = (const float*)d_in[6];  // (4,128,1)
  float* out = (float*)d_out;                // (4,2048,1024) fp32

  k0_init<<<128, 256>>>(Wq, Wk, a);
  k_pack<<<1024, 256>>>(adj);
  k1_wh<<<dim3(16, Hh, Bb), 256>>>(x, W, toh);
  k2_stats<<<dim3(8, 16, 4), 256>>>();
  k3_mma<<<dim3(16, Hh, Bb), 256>>>(out);
}